// round 1
// baseline (speedup 1.0000x reference)
#include <cuda_runtime.h>
#include <math.h>

#define Qn 1024
#define Tn 256
#define Nn 100
#define Kn 300      // 3*N flattened reduction dim
#define PITCH 306   // pred tile pitch: even (float2 align) and 306%32=18 -> bank-split q-lanes

__device__ float g_cls[Qn * 8];   // [0..3]=log(type_prob+eps), [4]=log(valid0+eps), [5..6]=log(closed+eps), [7]=p2
__device__ float g_v2[Tn];
__device__ int   g_lab[Tn];
__device__ int   g_clo[Tn];

// ---------------------------------------------------------------------------
// Precompute: per-q softmax logs + p2, per-t v2, int64/int32 label decode.
// ---------------------------------------------------------------------------
__global__ void pre_kernel(const float* __restrict__ pred,
                           const float* __restrict__ vlog,
                           const float* __restrict__ tlog,
                           const float* __restrict__ clog,
                           const float* __restrict__ tgt,
                           const int* __restrict__ lab32,
                           const int* __restrict__ clo32)
{
    const int tid = threadIdx.x;
    if (blockIdx.x < 4) {
        const int q = blockIdx.x * 256 + tid;
        // type softmax over 4
        float x0 = tlog[q*4+0], x1 = tlog[q*4+1], x2 = tlog[q*4+2], x3 = tlog[q*4+3];
        float m  = fmaxf(fmaxf(x0, x1), fmaxf(x2, x3));
        float e0 = expf(x0-m), e1 = expf(x1-m), e2 = expf(x2-m), e3 = expf(x3-m);
        float s  = e0 + e1 + e2 + e3;
        g_cls[q*8+0] = logf(e0/s + 1e-6f);
        g_cls[q*8+1] = logf(e1/s + 1e-6f);
        g_cls[q*8+2] = logf(e2/s + 1e-6f);
        g_cls[q*8+3] = logf(e3/s + 1e-6f);
        // valid softmax over 2, column 0
        float a0 = vlog[q*2+0], a1 = vlog[q*2+1];
        float ma = fmaxf(a0, a1);
        float f0 = expf(a0-ma), f1 = expf(a1-ma);
        g_cls[q*8+4] = logf(f0/(f0+f1) + 1e-6f);
        // closed softmax over 2, both columns
        float b0 = clog[q*2+0], b1 = clog[q*2+1];
        float mb = fmaxf(b0, b1);
        float h0 = expf(b0-mb), h1 = expf(b1-mb);
        float hs = h0 + h1;
        g_cls[q*8+5] = logf(h0/hs + 1e-6f);
        g_cls[q*8+6] = logf(h1/hs + 1e-6f);
        // p2[q] = sum of squared pred row
        float p2 = 0.f;
        for (int k = 0; k < Kn; k++) { float v = pred[q*Kn+k]; p2 = fmaf(v, v, p2); }
        g_cls[q*8+7] = p2;
    } else {
        // dtype detection: int64 data read as int32 has all odd words == 0
        __shared__ int flag;
        if (tid == 0) flag = 0;
        __syncthreads();
        if (tid < 128) {
            if (lab32[2*tid+1] != 0 || clo32[2*tid+1] != 0) atomicOr(&flag, 1);
        }
        __syncthreads();
        const int t = tid;  // 256 threads == Tn
        int lv, cv;
        if (flag) { lv = lab32[t]; cv = clo32[t]; }
        else {
            lv = (int)((const long long*)lab32)[t];
            cv = (int)((const long long*)clo32)[t];
        }
        g_lab[t] = lv;
        g_clo[t] = cv;
        float v2 = 0.f;
        for (int k = 0; k < Kn; k++) { float v = tgt[t*Kn+k]; v2 = fmaf(v, v, v2); }
        g_v2[t] = v2;
    }
}

// ---------------------------------------------------------------------------
// Main matcher kernel. Block = (t, 64-q tile).
// ---------------------------------------------------------------------------
__device__ __forceinline__ void epilogue_write(
    float best_ab, int ids, int t, int q, int clos,
    const float* __restrict__ clw, float* __restrict__ out, int write_ids)
{
    const float p2 = g_cls[q*8+7];
    float d2 = fmaxf(g_v2[t] + p2 - 2.0f * best_ab, 0.0f) / 100.0f;
    const int lab = g_lab[t];
    float cls = g_cls[q*8+lab] + g_cls[q*8+4] + g_cls[q*8+5+clos];
    float C = d2 * clw[t] - cls;
    out[q * Tn + t] = C;
    if (write_ids) out[Qn * Tn + q * Tn + t] = (float)ids;
}

__global__ void __launch_bounds__(256, 2)
match_kernel(const float* __restrict__ pred, const float* __restrict__ tgt,
             const float* __restrict__ clw, float* __restrict__ out, int write_ids)
{
    extern __shared__ float sm[];
    float* predsh = sm;                      // 64 * PITCH
    float* sf     = sm + 64 * PITCH;         // 608 (600 used): forward extended target
    float* sb     = sf + 608;                // 608: backward extended target
    float* redv   = sb + 608;                // 128: per-(dir,q) best ab
    int*   redi   = (int*)(redv + 128);      // 128: per-(dir,q) best idx

    const int t   = blockIdx.x;
    const int q0  = blockIdx.y * 64;
    const int tid = threadIdx.x;

    // stage pred tile: coalesced global read, conflict-free shared write
    for (int idx = tid; idx < 64 * Kn; idx += 256) {
        int q = idx / Kn;
        int k = idx - q * Kn;
        predsh[q * PITCH + k] = pred[q0 * Kn + idx];
    }
    // build extended target arrays: sf[m*3+c] = tgt[t][m%100][c], sb uses reversed rows
    for (int idx = tid; idx < 600; idx += 256) {
        int m  = idx / 3;
        int c  = idx - m * 3;
        int mm = (m >= Nn) ? (m - Nn) : m;
        sf[idx] = tgt[t*Kn + mm*3 + c];
        sb[idx] = tgt[t*Kn + (Nn-1-mm)*3 + c];
    }
    const int clos = g_clo[t];
    __syncthreads();

    if (clos) {
        // ---- heavy path: all 200 variants ----
        const int lane  = tid & 31;
        const int w     = tid >> 5;
        const int vlane = lane & 15;   // s addresses stride -3 across lanes: conflict-free
        const int qlane = lane >> 4;
        const int wq    = w & 3;
        const int dir   = w >> 2;      // 0 = fwd variants, 1 = bwd variants
        const float* sdir = dir ? sb : sf;
        const int qb = wq * 16 + qlane * 8;
        const float* pb = predsh + qb * PITCH;

        float acc[7][8];
        #pragma unroll
        for (int i = 0; i < 7; i++)
            #pragma unroll
            for (int u = 0; u < 8; u++) acc[i][u] = 0.f;

        int off[7];
        #pragma unroll
        for (int i = 0; i < 7; i++) {
            int v = vlane + 16 * i;
            if (v > 99) v = 99;            // clamped duplicates: harmless for max
            off[i] = (100 - v) * 3;
        }

        #pragma unroll 1
        for (int k = 0; k < Kn; k += 2) {
            float2 p[8];
            #pragma unroll
            for (int u = 0; u < 8; u++)
                p[u] = *(const float2*)(pb + u * PITCH + k);
            #pragma unroll
            for (int i = 0; i < 7; i++) {
                float s0 = sdir[k + off[i]];
                float s1 = sdir[k + 1 + off[i]];
                #pragma unroll
                for (int u = 0; u < 8; u++) {
                    acc[i][u] = fmaf(p[u].x, s0, acc[i][u]);
                    acc[i][u] = fmaf(p[u].y, s1, acc[i][u]);
                }
            }
        }

        // per-q max(ab) with first-index tie-break, reduce across 16 v-lanes
        #pragma unroll
        for (int u = 0; u < 8; u++) {
            float bv = acc[0][u];
            int   bx = (vlane > 99) ? 99 : vlane;
            #pragma unroll
            for (int i = 1; i < 7; i++) {
                int v = vlane + 16 * i;
                if (v > 99) v = 99;
                if (acc[i][u] > bv) { bv = acc[i][u]; bx = v; }   // strict >: keeps smaller v on tie
            }
            #pragma unroll
            for (int m = 8; m >= 1; m >>= 1) {
                float ov = __shfl_xor_sync(0xffffffffu, bv, m);
                int   ox = __shfl_xor_sync(0xffffffffu, bx, m);
                if (ov > bv || (ov == bv && ox < bx)) { bv = ov; bx = ox; }
            }
            if (vlane == 0) {
                redv[dir * 64 + qb + u] = bv;
                redi[dir * 64 + qb + u] = bx;
            }
        }
        __syncthreads();

        if (tid < 64) {
            float bf = redv[tid];      int xf = redi[tid];
            float bw = redv[64 + tid]; int xb = redi[64 + tid];
            float best; int ids;
            if (bw > bf) { best = bw; ids = 99 - xb; }  // bwd raw idx = 100+xb -> 2n-1-idx
            else         { best = bf; ids = xf; }       // tie -> fwd (smaller raw index)
            epilogue_write(best, ids, t, q0 + tid, clos, clw, out, write_ids);
        }
    } else {
        // ---- light path: open curve needs only variants v=0 (fwd) and v=n (bwd) ----
        if (tid < 64) {
            const float* pq = predsh + tid * PITCH;
            float af = 0.f, ab = 0.f;
            for (int k = 0; k < Kn; k++) {
                float p = pq[k];
                af = fmaf(p, sf[k + 300], af);
                ab = fmaf(p, sb[k + 300], ab);
            }
            float best = fmaxf(af, ab);   // min(d2_0, d2_n) == clamp of max ab
            epilogue_write(best, 0, t, q0 + tid, clos, clw, out, write_ids);
        }
    }
}

// ---------------------------------------------------------------------------
extern "C" void kernel_launch(void* const* d_in, const int* in_sizes, int n_in,
                              void* d_out, int out_size)
{
    const float* pred = (const float*)d_in[0];   // pred_curve_points (1,Q,N,3)
    const float* vlog = (const float*)d_in[1];   // pred_curve_logits (1,Q,2)
    const float* tlog = (const float*)d_in[2];   // pred_curve_type   (1,Q,4)
    const float* clog = (const float*)d_in[3];   // closed_curve_logits (1,Q,2)
    const float* tgt  = (const float*)d_in[4];   // tgt_curve_points (T,N,3)
    const int*   lab  = (const int*)d_in[5];     // tgt_labels (int32 or int64)
    const int*   clo  = (const int*)d_in[6];     // tgt_is_closed
    const float* clw  = (const float*)d_in[7];   // curve_length_weighting (T)
    float* out = (float*)d_out;

    const int smem = (64 * PITCH + 608 * 2 + 128) * (int)sizeof(float) + 128 * (int)sizeof(int);
    cudaFuncSetAttribute(match_kernel, cudaFuncAttributeMaxDynamicSharedMemorySize, smem);

    const int write_ids = (out_size >= 2 * Qn * Tn) ? 1 : 0;

    pre_kernel<<<5, 256>>>(pred, vlog, tlog, clog, tgt, lab, clo);
    match_kernel<<<dim3(Tn, 16), 256, smem>>>(pred, tgt, clw, out, write_ids);
}